// round 1
// baseline (speedup 1.0000x reference)
#include <cuda_runtime.h>
#include <cstdint>

// Problem constants (fixed shapes)
#define Bc 16
#define Cc 3
#define Hc 1024
#define Wc 1024
#define NF 15728

// 16 MB per-(b,y,x) flake mask scratch (device global: allocation-guard safe)
__device__ uint8_t g_mask[(size_t)Bc * Hc * Wc];

// ---------------------------------------------------------------------------
// 1) clear mask: 16 MB of zeros, vectorized 16B stores
// ---------------------------------------------------------------------------
__global__ void hs_clear_mask() {
    size_t i = (size_t)blockIdx.x * blockDim.x + threadIdx.x;
    reinterpret_cast<float4*>(g_mask)[i] = make_float4(0.f, 0.f, 0.f, 0.f);
}

// ---------------------------------------------------------------------------
// 2) stamp flakes: one warp per flake, lanes cover the (2r+1)^2 square.
//    OOB offsets are skipped (equivalent to reference's clamp-to-border,
//    since the clamped pixel is always covered by an in-range offset).
// ---------------------------------------------------------------------------
__global__ void hs_stamp(const int* __restrict__ ys,
                         const int* __restrict__ xs,
                         const int* __restrict__ rs) {
    int warp = (int)((blockIdx.x * blockDim.x + threadIdx.x) >> 5);
    int lane = threadIdx.x & 31;
    if (warp >= Bc * NF) return;
    int b = warp / NF;
    int n = warp - b * NF;
    int idx = b * NF + n;
    int cy = ys[idx];
    int cx = xs[idx];
    int r  = rs[idx];
    int side = 2 * r + 1;
    int np = side * side;   // <= 49
    uint8_t* mb = g_mask + (size_t)b * Hc * Wc;
    for (int i = lane; i < np; i += 32) {
        int row = i / side;             // side in {3,5,7}
        int dy = row - r;
        int dx = (i - row * side) - r;
        int y = cy + dy;
        int x = cx + dx;
        if ((unsigned)y < Hc && (unsigned)x < Wc)
            mb[(size_t)y * Wc + x] = (uint8_t)1;
    }
}

// ---------------------------------------------------------------------------
// 3) fused composite + separable 5x5 gaussian blur + clip
//    Output tile: 128 x 32 per block, 256 threads.
//    Stage tile:  136 x 36 (halo 2, padded to 16B-aligned float4 loads).
// ---------------------------------------------------------------------------
#define TX 128
#define TY 32
#define SW 136     // staged width  (gx0-4 .. gx0+131), always 16B aligned
#define SH 36      // staged height (gy0-2 .. gy0+33)

// Gaussian weights: g = exp(-c^2/(2*1.5^2)), c in [-2..2], normalized.
#define W0 0.12007829f
#define W1 0.23388140f
#define W2 0.29208061f

__global__ __launch_bounds__(256) void hs_blur(const float* __restrict__ xin,
                                               float* __restrict__ out) {
    __shared__ float s_in[SH][SW];
    __shared__ float s_h [SH][TX];

    const int gx0 = blockIdx.x * TX;
    const int gy0 = blockIdx.y * TY;
    const int z   = blockIdx.z;          // b*C + c
    const int b   = z / Cc;
    const float*   xp = xin + (size_t)z * Hc * Wc;
    const uint8_t* mp = g_mask + (size_t)b * Hc * Wc;
    const int tid = threadIdx.x;

    // -- load + composite (zero pad outside image) --
    // each float4 column group is either fully in-bounds or fully out (W%128==0)
    #pragma unroll
    for (int i = 0; i < 5; i++) {
        int idx = tid + i * 256;
        if (idx < (SW / 4) * SH) {
            int row = idx / (SW / 4);
            int c4  = idx - row * (SW / 4);
            int gy  = gy0 - 2 + row;
            int gxa = gx0 - 4 + c4 * 4;
            float4 v = make_float4(0.f, 0.f, 0.f, 0.f);
            if ((unsigned)gy < Hc && (unsigned)gxa < Wc) {
                v = *reinterpret_cast<const float4*>(xp + (size_t)gy * Wc + gxa);
                uchar4 m = *reinterpret_cast<const uchar4*>(mp + (size_t)gy * Wc + gxa);
                if (m.x) v.x = 0.95f;
                if (m.y) v.y = 0.95f;
                if (m.z) v.z = 0.95f;
                if (m.w) v.w = 0.95f;
            }
            *reinterpret_cast<float4*>(&s_in[row][c4 * 4]) = v;
        }
    }
    __syncthreads();

    // -- horizontal pass: s_h[row][j] for j in [0,128) --
    #pragma unroll
    for (int i = 0; i < (SH * TX) / 256; i++) {
        int idx = tid + i * 256;
        int row = idx >> 7;       // / 128
        int j   = idx & 127;
        const float* rp = &s_in[row][j];
        s_h[row][j] = W0 * (rp[2] + rp[6]) + W1 * (rp[3] + rp[5]) + W2 * rp[4];
    }
    __syncthreads();

    // -- vertical pass + clip + float4 store --
    #pragma unroll
    for (int e0 = 0; e0 < (TY * (TX / 4)) / 256; e0++) {
        int e = tid + e0 * 256;
        int i = e >> 5;           // / 32  -> output row in tile
        int q = e & 31;
        int j = 4 * q;
        float4 o;
        float* po = &o.x;
        #pragma unroll
        for (int k = 0; k < 4; k++) {
            float v = W0 * (s_h[i][j + k] + s_h[i + 4][j + k])
                    + W1 * (s_h[i + 1][j + k] + s_h[i + 3][j + k])
                    + W2 *  s_h[i + 2][j + k];
            po[k] = fminf(fmaxf(v, 0.f), 1.f);
        }
        *reinterpret_cast<float4*>(out + (size_t)z * Hc * Wc
                                   + (size_t)(gy0 + i) * Wc + gx0 + j) = o;
    }
}

// ---------------------------------------------------------------------------
extern "C" void kernel_launch(void* const* d_in, const int* in_sizes, int n_in,
                              void* d_out, int out_size) {
    const float* x  = (const float*)d_in[0];
    const int*   ys = (const int*)d_in[1];
    const int*   xs = (const int*)d_in[2];
    const int*   rs = (const int*)d_in[3];
    float* out = (float*)d_out;

    // 1) clear mask: 16 MB / 16B = 1,048,576 stores
    hs_clear_mask<<<4096, 256>>>();

    // 2) stamp: warp per flake
    int total_flakes = Bc * NF;                 // 251,648
    int warps_per_blk = 8;                      // 256 threads
    int nblk = (total_flakes + warps_per_blk - 1) / warps_per_blk;
    hs_stamp<<<nblk, 256>>>(ys, xs, rs);

    // 3) fused composite + blur + clip
    dim3 grid(Wc / TX, Hc / TY, Bc * Cc);       // (8, 32, 48)
    hs_blur<<<grid, 256>>>(x, out);
}

// round 2
// speedup vs baseline: 1.0357x; 1.0357x over previous
#include <cuda_runtime.h>
#include <cstdint>

// Problem constants (fixed shapes)
#define Bc 16
#define Cc 3
#define Hc 1024
#define Wc 1024
#define NF 15728

// 16 MB per-(b,y,x) flake mask scratch (device global: allocation-guard safe)
__device__ uint8_t g_mask[(size_t)Bc * Hc * Wc];

// ---------------------------------------------------------------------------
// 1) clear mask: 16 MB of zeros, vectorized 16B stores
// ---------------------------------------------------------------------------
__global__ void hs_clear_mask() {
    size_t i = (size_t)blockIdx.x * blockDim.x + threadIdx.x;
    reinterpret_cast<float4*>(g_mask)[i] = make_float4(0.f, 0.f, 0.f, 0.f);
}

// ---------------------------------------------------------------------------
// 2) stamp flakes: one warp per flake, lanes cover the (2r+1)^2 square.
//    OOB offsets are skipped (equivalent to reference's clamp-to-border,
//    since the clamped pixel is always covered by an in-range offset).
// ---------------------------------------------------------------------------
__global__ void hs_stamp(const int* __restrict__ ys,
                         const int* __restrict__ xs,
                         const int* __restrict__ rs) {
    int warp = (int)((blockIdx.x * blockDim.x + threadIdx.x) >> 5);
    int lane = threadIdx.x & 31;
    if (warp >= Bc * NF) return;
    int b = warp / NF;
    int idx = warp;                 // already b*NF + n
    int cy = ys[idx];
    int cx = xs[idx];
    int r  = rs[idx];
    int side = 2 * r + 1;
    int np = side * side;           // <= 49
    uint8_t* mb = g_mask + (size_t)b * Hc * Wc;
    for (int i = lane; i < np; i += 32) {
        int row = i / side;         // side in {3,5,7}
        int dy = row - r;
        int dx = (i - row * side) - r;
        int y = cy + dy;
        int x = cx + dx;
        if ((unsigned)y < Hc && (unsigned)x < Wc)
            mb[(size_t)y * Wc + x] = (uint8_t)1;
    }
}

// ---------------------------------------------------------------------------
// 3) fused composite + separable 5x5 gaussian blur + clip
//    Tile: 128 x 64 outputs per block, 256 threads.
//    Thread layout: lane (tid&31) owns 4 consecutive columns (LDS.128),
//                   strip (tid>>5) owns 8 consecutive output rows.
//    Horizontal blur via 3 conflict-free LDS.128 per row; vertical blur via
//    5-entry float4 register ring (zero smem traffic for the 2nd pass).
// ---------------------------------------------------------------------------
#define TX 128
#define TY 64
#define RS 8       // output rows per strip
#define SW 136     // staged width  (gx0-4 .. gx0+131), 16B aligned rows
#define SH 68      // staged height (gy0-2 .. gy0+65)

// Gaussian weights: g = exp(-c^2/(2*1.5^2)), c in [-2..2], normalized.
#define W0 0.12007829f
#define W1 0.23388140f
#define W2 0.29208061f

__device__ __forceinline__ float4 f4_fma5(float4 a, float4 b, float4 c,
                                          float4 d, float4 e) {
    // W0*(a+e) + W1*(b+d) + W2*c
    float4 o;
    o.x = W0 * (a.x + e.x) + W1 * (b.x + d.x) + W2 * c.x;
    o.y = W0 * (a.y + e.y) + W1 * (b.y + d.y) + W2 * c.y;
    o.z = W0 * (a.z + e.z) + W1 * (b.z + d.z) + W2 * c.z;
    o.w = W0 * (a.w + e.w) + W1 * (b.w + d.w) + W2 * c.w;
    return o;
}

__global__ __launch_bounds__(256) void hs_blur(const float* __restrict__ xin,
                                               float* __restrict__ out) {
    __shared__ float s_in[SH][SW];

    const int gx0 = blockIdx.x * TX;
    const int gy0 = blockIdx.y * TY;
    const int z   = blockIdx.z;          // b*C + c
    const int b   = z / Cc;
    const float*   xp = xin + (size_t)z * Hc * Wc;
    const uint8_t* mp = g_mask + (size_t)b * Hc * Wc;
    const int tid = threadIdx.x;

    // -- load + composite (zero pad outside image) --
    // SW/4 = 34 float4 per row, SH = 68 rows -> 2312 float4 tasks
    #pragma unroll
    for (int i = 0; i < 10; i++) {
        int idx = tid + i * 256;
        if (idx < 34 * SH) {
            int row = idx / 34;
            int c4  = idx - row * 34;
            int gy  = gy0 - 2 + row;
            int gxa = gx0 - 4 + c4 * 4;
            float4 v = make_float4(0.f, 0.f, 0.f, 0.f);
            if ((unsigned)gy < Hc && (unsigned)gxa < Wc) {
                v = *reinterpret_cast<const float4*>(xp + (size_t)gy * Wc + gxa);
                uchar4 m = *reinterpret_cast<const uchar4*>(mp + (size_t)gy * Wc + gxa);
                if (m.x) v.x = 0.95f;
                if (m.y) v.y = 0.95f;
                if (m.z) v.z = 0.95f;
                if (m.w) v.w = 0.95f;
            }
            *reinterpret_cast<float4*>(&s_in[row][c4 * 4]) = v;
        }
    }
    __syncthreads();

    const int lane  = tid & 31;
    const int strip = tid >> 5;          // 0..7
    const int row0  = strip * RS;        // s_in row for t=0 (= out row - 2)
    float* obase = out + (size_t)z * Hc * Wc
                 + (size_t)(gy0 + strip * RS) * Wc + gx0 + 4 * lane;

    float4 h[5];
    #pragma unroll
    for (int t = 0; t < RS + 4; t++) {
        // horizontal pass for s_in row (row0 + t): 3 aligned LDS.128
        const float* p = &s_in[row0 + t][4 * lane];
        float4 A = *reinterpret_cast<const float4*>(p);
        float4 Bv = *reinterpret_cast<const float4*>(p + 4);
        float4 Cv = *reinterpret_cast<const float4*>(p + 8);
        float q0 = A.x, q1 = A.y, q2 = A.z, q3 = A.w;
        float q4 = Bv.x, q5 = Bv.y, q6 = Bv.z, q7 = Bv.w;
        float q8 = Cv.x, q9 = Cv.y;
        float4 hv;
        hv.x = W0 * (q2 + q6) + W1 * (q3 + q5) + W2 * q4;
        hv.y = W0 * (q3 + q7) + W1 * (q4 + q6) + W2 * q5;
        hv.z = W0 * (q4 + q8) + W1 * (q5 + q7) + W2 * q6;
        hv.w = W0 * (q5 + q9) + W1 * (q6 + q8) + W2 * q7;
        h[t % 5] = hv;

        if (t >= 4) {
            // vertical pass for output row (t-4) of this strip
            float4 o = f4_fma5(h[(t - 4) % 5], h[(t - 3) % 5], h[(t - 2) % 5],
                               h[(t - 1) % 5], h[t % 5]);
            o.x = fminf(fmaxf(o.x, 0.f), 1.f);
            o.y = fminf(fmaxf(o.y, 0.f), 1.f);
            o.z = fminf(fmaxf(o.z, 0.f), 1.f);
            o.w = fminf(fmaxf(o.w, 0.f), 1.f);
            *reinterpret_cast<float4*>(obase + (size_t)(t - 4) * Wc) = o;
        }
    }
}

// ---------------------------------------------------------------------------
extern "C" void kernel_launch(void* const* d_in, const int* in_sizes, int n_in,
                              void* d_out, int out_size) {
    const float* x  = (const float*)d_in[0];
    const int*   ys = (const int*)d_in[1];
    const int*   xs = (const int*)d_in[2];
    const int*   rs = (const int*)d_in[3];
    float* out = (float*)d_out;

    // 1) clear mask: 16 MB / 16B = 1,048,576 float4 stores
    hs_clear_mask<<<4096, 256>>>();

    // 2) stamp: warp per flake
    int total_flakes = Bc * NF;                 // 251,648
    int warps_per_blk = 8;                      // 256 threads
    int nblk = (total_flakes + warps_per_blk - 1) / warps_per_blk;
    hs_stamp<<<nblk, 256>>>(ys, xs, rs);

    // 3) fused composite + blur + clip
    dim3 grid(Wc / TX, Hc / TY, Bc * Cc);       // (8, 16, 48)
    hs_blur<<<grid, 256>>>(x, out);
}

// round 3
// speedup vs baseline: 1.4196x; 1.3707x over previous
#include <cuda_runtime.h>
#include <cstdint>

// Problem constants (fixed shapes)
#define Bc 16
#define Cc 3
#define Hc 1024
#define Wc 1024
#define NF 15728
#define WW (Wc / 32)          // 32 bit-words per row

// 2 MB per-(b,y,x) flake BITmask scratch (device global: allocation-guard safe)
__device__ uint32_t g_bits[(size_t)Bc * Hc * WW];

// ---------------------------------------------------------------------------
// 1) clear bitmask: 2 MB of zeros, vectorized 16B stores
// ---------------------------------------------------------------------------
__global__ void hs_clear_mask() {
    size_t i = (size_t)blockIdx.x * blockDim.x + threadIdx.x;
    reinterpret_cast<uint4*>(g_bits)[i] = make_uint4(0u, 0u, 0u, 0u);
}

// ---------------------------------------------------------------------------
// 2) stamp flakes: one THREAD per flake; each of the <=7 rows becomes 1-2
//    atomicOr (REDG) into the L2-resident bitmask. OOB rows/cols are clipped
//    (equivalent to reference's clamp-to-border: the clamped pixel is always
//    covered by an in-range offset).
// ---------------------------------------------------------------------------
__global__ void hs_stamp(const int* __restrict__ ys,
                         const int* __restrict__ xs,
                         const int* __restrict__ rs) {
    int idx = blockIdx.x * blockDim.x + threadIdx.x;
    if (idx >= Bc * NF) return;
    int b  = idx / NF;
    int cy = ys[idx];
    int cx = xs[idx];
    int r  = rs[idx];

    int x0 = max(cx - r, 0);
    int x1 = min(cx + r, Wc - 1);
    int w0 = x0 >> 5;
    uint64_t m  = ((1ull << (x1 - x0 + 1)) - 1ull) << (x0 & 31);
    uint32_t lo = (uint32_t)m;
    uint32_t hi = (uint32_t)(m >> 32);

    uint32_t* bb = g_bits + (size_t)b * Hc * WW;
    #pragma unroll
    for (int dy = -3; dy <= 3; dy++) {
        if (dy < -r || dy > r) continue;
        int y = cy + dy;
        if ((unsigned)y >= Hc) continue;
        uint32_t* row = bb + (size_t)y * WW;
        atomicOr(&row[w0], lo);
        if (hi) atomicOr(&row[w0 + 1], hi);
    }
}

// ---------------------------------------------------------------------------
// 3) fused composite + separable 5x5 gaussian blur + clip
//    Tile: 128 x 64 outputs per block, 256 threads = 8 strips x 32 lanes.
//    Conflict-free LDS.128 horizontal pass, register-ring vertical pass.
//    Streaming x loads / out stores (__ldcs/__stcs) keep bitmask L2-hot.
// ---------------------------------------------------------------------------
#define TX 128
#define TY 64
#define RS 8       // output rows per strip
#define SW 136     // staged width  (gx0-4 .. gx0+131), 16B aligned rows
#define SH 68      // staged height (gy0-2 .. gy0+65)

// Gaussian weights: g = exp(-c^2/(2*1.5^2)), c in [-2..2], normalized.
#define W0 0.12007829f
#define W1 0.23388140f
#define W2 0.29208061f

__global__ __launch_bounds__(256) void hs_blur(const float* __restrict__ xin,
                                               float* __restrict__ out) {
    __shared__ float s_in[SH][SW];

    const int gx0 = blockIdx.x * TX;
    const int gy0 = blockIdx.y * TY;
    const int z   = blockIdx.z;          // b*C + c
    const int b   = z / Cc;
    const float*    xp = xin + (size_t)z * Hc * Wc;
    const uint32_t* bp = g_bits + (size_t)b * Hc * WW;
    const int tid = threadIdx.x;

    // -- load + composite (zero pad outside image) --
    // SW/4 = 34 float4 per row, SH = 68 rows -> 2312 float4 tasks
    #pragma unroll
    for (int i = 0; i < 10; i++) {
        int idx = tid + i * 256;
        if (idx < 34 * SH) {
            int row = idx / 34;
            int c4  = idx - row * 34;
            int gy  = gy0 - 2 + row;
            int gxa = gx0 - 4 + c4 * 4;
            float4 v = make_float4(0.f, 0.f, 0.f, 0.f);
            if ((unsigned)gy < Hc && (unsigned)gxa < Wc) {
                v = __ldcs(reinterpret_cast<const float4*>(
                        xp + (size_t)gy * Wc + gxa));
                uint32_t w = bp[(size_t)gy * WW + (gxa >> 5)];
                if (w) {
                    uint32_t nib = (w >> (gxa & 31)) & 0xFu;
                    if (nib & 1u) v.x = 0.95f;
                    if (nib & 2u) v.y = 0.95f;
                    if (nib & 4u) v.z = 0.95f;
                    if (nib & 8u) v.w = 0.95f;
                }
            }
            *reinterpret_cast<float4*>(&s_in[row][c4 * 4]) = v;
        }
    }
    __syncthreads();

    const int lane  = tid & 31;
    const int strip = tid >> 5;          // 0..7
    const int row0  = strip * RS;        // s_in row for t=0 (= out row - 2)
    float* obase = out + (size_t)z * Hc * Wc
                 + (size_t)(gy0 + strip * RS) * Wc + gx0 + 4 * lane;

    float4 h[5];
    #pragma unroll
    for (int t = 0; t < RS + 4; t++) {
        // horizontal pass for s_in row (row0 + t): 3 aligned LDS.128
        const float* p = &s_in[row0 + t][4 * lane];
        float4 A  = *reinterpret_cast<const float4*>(p);
        float4 Bv = *reinterpret_cast<const float4*>(p + 4);
        float4 Cv = *reinterpret_cast<const float4*>(p + 8);
        float q2 = A.z, q3 = A.w;
        float q4 = Bv.x, q5 = Bv.y, q6 = Bv.z, q7 = Bv.w;
        float q8 = Cv.x, q9 = Cv.y;
        float4 hv;
        hv.x = W0 * (q2 + q6) + W1 * (q3 + q5) + W2 * q4;
        hv.y = W0 * (q3 + q7) + W1 * (q4 + q6) + W2 * q5;
        hv.z = W0 * (q4 + q8) + W1 * (q5 + q7) + W2 * q6;
        hv.w = W0 * (q5 + q9) + W1 * (q6 + q8) + W2 * q7;
        h[t % 5] = hv;

        if (t >= 4) {
            // vertical pass for output row (t-4) of this strip
            float4 a = h[(t - 4) % 5], bb2 = h[(t - 3) % 5], c = h[(t - 2) % 5];
            float4 d = h[(t - 1) % 5], e = h[t % 5];
            float4 o;
            o.x = W0 * (a.x + e.x) + W1 * (bb2.x + d.x) + W2 * c.x;
            o.y = W0 * (a.y + e.y) + W1 * (bb2.y + d.y) + W2 * c.y;
            o.z = W0 * (a.z + e.z) + W1 * (bb2.z + d.z) + W2 * c.z;
            o.w = W0 * (a.w + e.w) + W1 * (bb2.w + d.w) + W2 * c.w;
            o.x = fminf(fmaxf(o.x, 0.f), 1.f);
            o.y = fminf(fmaxf(o.y, 0.f), 1.f);
            o.z = fminf(fmaxf(o.z, 0.f), 1.f);
            o.w = fminf(fmaxf(o.w, 0.f), 1.f);
            __stcs(reinterpret_cast<float4*>(obase + (size_t)(t - 4) * Wc), o);
        }
    }
}

// ---------------------------------------------------------------------------
extern "C" void kernel_launch(void* const* d_in, const int* in_sizes, int n_in,
                              void* d_out, int out_size) {
    const float* x  = (const float*)d_in[0];
    const int*   ys = (const int*)d_in[1];
    const int*   xs = (const int*)d_in[2];
    const int*   rs = (const int*)d_in[3];
    float* out = (float*)d_out;

    // 1) clear bitmask: 2 MB / 16B = 131,072 uint4 stores
    hs_clear_mask<<<512, 256>>>();

    // 2) stamp: thread per flake
    int total_flakes = Bc * NF;                 // 251,648
    hs_stamp<<<(total_flakes + 255) / 256, 256>>>(ys, xs, rs);

    // 3) fused composite + blur + clip
    dim3 grid(Wc / TX, Hc / TY, Bc * Cc);       // (8, 16, 48)
    hs_blur<<<grid, 256>>>(x, out);
}